// round 7
// baseline (speedup 1.0000x reference)
#include <cuda_runtime.h>
#include <cuda_bf16.h>
#include <math.h>
#include <stdint.h>
#include <string.h>

#define BB 2
#define SS 2048
#define DD 1024
#define HH 16
#define DK 64
#define MM (BB*SS)   // 4096

// ---------------- scratch (static device memory; no allocations) ----------------
__device__ float g_Qraw[BB*SS*DD];   // [B,S,H*dk] post-projection (pre-rope)
__device__ float g_Kraw[BB*SS*DD];
__device__ float g_Vraw[BB*SS*DD];
__device__ float g_attn[BB*SS*DD];   // [B,S,D]

// ---------------- TF32 helpers (GEMMs) ----------------
__device__ __forceinline__ float to_tf32(float x) {
    float y;
    asm("cvt.rna.tf32.f32 %0, %1;" : "=f"(y) : "f"(x));
    return y;
}

__device__ __forceinline__ void mma_tf32(float c[4],
                                         uint32_t a0, uint32_t a1, uint32_t a2, uint32_t a3,
                                         uint32_t b0, uint32_t b1)
{
    asm volatile("mma.sync.aligned.m16n8k8.row.col.f32.tf32.tf32.f32 "
                 "{%0,%1,%2,%3}, {%4,%5,%6,%7}, {%8,%9}, {%0,%1,%2,%3};"
                 : "+f"(c[0]), "+f"(c[1]), "+f"(c[2]), "+f"(c[3])
                 : "r"(a0), "r"(a1), "r"(a2), "r"(a3), "r"(b0), "r"(b1));
}

// ---------------- BF16 helpers (attention) ----------------
__device__ __forceinline__ void mma_bf16(float c[4],
                                         uint32_t a0, uint32_t a1, uint32_t a2, uint32_t a3,
                                         uint32_t b0, uint32_t b1)
{
    asm volatile("mma.sync.aligned.m16n8k16.row.col.f32.bf16.bf16.f32 "
                 "{%0,%1,%2,%3}, {%4,%5,%6,%7}, {%8,%9}, {%0,%1,%2,%3};"
                 : "+f"(c[0]), "+f"(c[1]), "+f"(c[2]), "+f"(c[3])
                 : "r"(a0), "r"(a1), "r"(a2), "r"(a3), "r"(b0), "r"(b1));
}

// hi = bf16x2(x,y), lo = bf16x2(x-hi.x, y-hi.y); packed as uint32 (even in low half)
__device__ __forceinline__ void split_bf16(float x, float y, uint32_t& hi, uint32_t& lo)
{
    __nv_bfloat162 h = __floats2bfloat162_rn(x, y);
    float hx = __bfloat162float(h.x);
    float hy = __bfloat162float(h.y);
    __nv_bfloat162 l = __floats2bfloat162_rn(x - hx, y - hy);
    hi = *reinterpret_cast<uint32_t*>(&h);
    lo = *reinterpret_cast<uint32_t*>(&l);
}

// ---------------- TF32 GEMM: C[4096,1024] = A[4096,1024] @ W[1024,1024] ----------------
#define AS_STRIDE 20
#define BS_STRIDE 136

__global__ void __launch_bounds__(256, 2)
gemm_tf32_kernel(const float* __restrict__ A, const float* __restrict__ W,
                 float* __restrict__ C)
{
    const int K = 1024, N = 1024;
    __shared__ float As[128 * AS_STRIDE];
    __shared__ float Bs[16 * BS_STRIDE];

    const int tid  = threadIdx.x;
    const int warp = tid >> 5;
    const int lane = tid & 31;
    const int g = lane >> 2;
    const int t = lane & 3;

    const int wm = warp & 1;
    const int wn = warp >> 1;
    const int warp_m = wm * 64;
    const int warp_n = wn * 32;

    const int row0 = blockIdx.y * 128;
    const int col0 = blockIdx.x * 128;

    const int a_row = tid >> 1;
    const int a_cg  = (tid & 1) * 8;
    const int b_row = tid >> 4;
    const int b_col = (tid & 15) * 8;

    float acc[4][4][4];
    #pragma unroll
    for (int i = 0; i < 4; i++)
        #pragma unroll
        for (int j = 0; j < 4; j++)
            #pragma unroll
            for (int r = 0; r < 4; r++)
                acc[i][j][r] = 0.0f;

    for (int k0 = 0; k0 < K; k0 += 16) {
        {
            const float4* src = (const float4*)&A[(long)(row0 + a_row) * K + k0 + a_cg];
            float4 v0 = src[0];
            float4 v1 = src[1];
            float4 w0 = make_float4(to_tf32(v0.x), to_tf32(v0.y), to_tf32(v0.z), to_tf32(v0.w));
            float4 w1 = make_float4(to_tf32(v1.x), to_tf32(v1.y), to_tf32(v1.z), to_tf32(v1.w));
            float4* dst = (float4*)&As[a_row * AS_STRIDE + a_cg];
            dst[0] = w0;
            dst[1] = w1;
        }
        {
            const float4* src = (const float4*)&W[(long)(k0 + b_row) * N + col0 + b_col];
            float4 v0 = src[0];
            float4 v1 = src[1];
            float4 w0 = make_float4(to_tf32(v0.x), to_tf32(v0.y), to_tf32(v0.z), to_tf32(v0.w));
            float4 w1 = make_float4(to_tf32(v1.x), to_tf32(v1.y), to_tf32(v1.z), to_tf32(v1.w));
            float4* dst = (float4*)&Bs[b_row * BS_STRIDE + b_col];
            dst[0] = w0;
            dst[1] = w1;
        }
        __syncthreads();

        #pragma unroll
        for (int chunk = 0; chunk < 2; chunk++) {
            const int kc = chunk * 8;

            uint32_t af[4][4];
            #pragma unroll
            for (int fm = 0; fm < 4; fm++) {
                int mrow = warp_m + fm * 16 + g;
                const float* pa = &As[mrow * AS_STRIDE + kc + t];
                af[fm][0] = __float_as_uint(pa[0]);
                af[fm][1] = __float_as_uint(pa[8 * AS_STRIDE]);
                af[fm][2] = __float_as_uint(pa[4]);
                af[fm][3] = __float_as_uint(pa[8 * AS_STRIDE + 4]);
            }
            uint32_t bf[4][2];
            #pragma unroll
            for (int fn = 0; fn < 4; fn++) {
                const float* pb = &Bs[(kc + t) * BS_STRIDE + warp_n + fn * 8 + g];
                bf[fn][0] = __float_as_uint(pb[0]);
                bf[fn][1] = __float_as_uint(pb[4 * BS_STRIDE]);
            }

            #pragma unroll
            for (int fm = 0; fm < 4; fm++)
                #pragma unroll
                for (int fn = 0; fn < 4; fn++)
                    mma_tf32(acc[fm][fn],
                             af[fm][0], af[fm][1], af[fm][2], af[fm][3],
                             bf[fn][0], bf[fn][1]);
        }
        __syncthreads();
    }

    #pragma unroll
    for (int fm = 0; fm < 4; fm++) {
        #pragma unroll
        for (int fn = 0; fn < 4; fn++) {
            int r0 = row0 + warp_m + fm * 16 + g;
            int c0 = col0 + warp_n + fn * 8 + 2 * t;
            float2* p0 = (float2*)&C[(long)r0 * N + c0];
            *p0 = make_float2(acc[fm][fn][0], acc[fm][fn][1]);
            float2* p1 = (float2*)&C[(long)(r0 + 8) * N + c0];
            *p1 = make_float2(acc[fm][fn][2], acc[fm][fn][3]);
        }
    }
}

// ---------------- flash attention (3xBF16 mma m16n8k16, causal, fused RoPE) ----------------
// Br=64 (4 warps x 16 rows), Bc=32. Q/K/V staged directly from the raw
// [B,S,H*dk] projections; RoPE applied to Q/K pairs during staging.
// Q/K/V pre-split into packed bf16x2 hi/lo planes in smem; P stays in
// registers (S C-frags map directly onto PV A-frags).
//
// smem word map (uint32):
//  sQ : [pl][64 rows][32 w]  idx = pl*2048 + (r<<5) + (w ^ ((r&7)<<2))          @ 0
//  sK : [buf][pl][32 r][32 w] idx = 4096 + buf*2048 + pl*1024 + (r<<5) + (w^((r&7)<<2))
//  sVT: [buf][pl][64 n][16 kp] idx = 8192 + buf*2048 + pl*1024 + (n<<4) + (kp^(((n>>1)&3)<<2))
#define ATT_SMEM_WORDS 12288   // 49152 bytes

__global__ void __launch_bounds__(128, 3)
flash_attn_kernel(const int* __restrict__ tpos,
                  const float* __restrict__ cosT,
                  const float* __restrict__ sinT)
{
    extern __shared__ uint32_t smw[];

    const int tid  = threadIdx.x;
    const int warp = tid >> 5;
    const int lane = tid & 31;
    const int g = lane >> 2;
    const int t = lane & 3;

    const int bx = gridDim.x - 1 - blockIdx.x;   // heavy tiles first
    const int bh = blockIdx.y;
    const int b = bh >> 4, h = bh & 15;
    const int q0 = bx * 64;
    const long hoff = (long)h * DK;

    // ---- stage Q once (RoPE + scale 1/8 + bf16 hi/lo planes) ----
    {
        const int row = tid >> 1;
        const int srow = q0 + row;
        const int p = tpos[srow];
        const float* Qr = g_Qraw + (long)(b * SS + srow) * DD + hoff;
        const float* ct = cosT + p * 32;
        const float* st = sinT + p * 32;
        #pragma unroll
        for (int s = 0; s < 16; s++) {
            const int w = (tid & 1) + 2 * s;       // pair index 0..31
            float2 v = *(const float2*)(Qr + 2 * w);
            const float c  = ct[w];
            const float sn = st[w];
            const float xe = (c * v.x - sn * v.y) * 0.125f;
            const float xo = (sn * v.x + c * v.y) * 0.125f;
            uint32_t hi, lo;
            split_bf16(xe, xo, hi, lo);
            const int idx = (row << 5) + (w ^ ((row & 7) << 2));
            smw[idx]        = hi;
            smw[2048 + idx] = lo;
        }
    }

    // staging thread assignments
    const int kr  = tid >> 2;         // K: row 0..31
    const int kq  = tid & 3;          // K: word phase
    const int vkp = tid >> 3;         // V: key-pair 0..15
    const int vn  = tid & 7;          // V: dim phase

    float2 kreg[8];
    float  va[8], vb[8];

    // prefetch + rope tile 0 into regs
    {
        const int krow = kr;                       // kt=0
        const int p = tpos[krow];
        const float* Kr = g_Kraw + (long)(b * SS + krow) * DD + hoff;
        const float* ct = cosT + p * 32;
        const float* st = sinT + p * 32;
        #pragma unroll
        for (int s = 0; s < 8; s++) {
            const int pi = kq + 4 * s;             // pair index
            float2 v = *(const float2*)(Kr + 2 * pi);
            const float c  = ct[pi];
            const float sn = st[pi];
            kreg[s] = make_float2(c * v.x - sn * v.y, sn * v.x + c * v.y);
        }
        const float* Vr0 = g_Vraw + (long)(b * SS + 2 * vkp)     * DD + hoff;
        const float* Vr1 = g_Vraw + (long)(b * SS + 2 * vkp + 1) * DD + hoff;
        #pragma unroll
        for (int i = 0; i < 8; i++) {
            va[i] = Vr0[vn + 8 * i];
            vb[i] = Vr1[vn + 8 * i];
        }
    }

    // softmax state
    float m0 = -1e30f, m1 = -1e30f, l0 = 0.0f, l1 = 0.0f;
    float O[8][4];
    #pragma unroll
    for (int fn = 0; fn < 8; fn++)
        #pragma unroll
        for (int r = 0; r < 4; r++)
            O[fn][r] = 0.0f;

    const int pr0 = warp * 16 + g;
    const int r0g = q0 + pr0;
    const int r1g = r0g + 8;
    const int ntiles = 2 * bx + 2;

    const int qsw = (pr0 & 7) << 2;          // == g<<2
    const int vsw = ((g >> 1) & 3) << 2;     // V row swizzle: ((n>>1)&3)<<2 with n=fn*8+g

    for (int kt = 0; kt < ntiles; kt++) {
        const int cur = kt & 1;

        __syncthreads();   // readers of this buffer (tile kt-2) done; Q staged (kt=0)

        // ---- split + store tile kt (from regs) into smem buffer cur ----
        {
            const int kbase = 4096 + cur * 2048;
            #pragma unroll
            for (int s = 0; s < 8; s++) {
                uint32_t hi, lo;
                split_bf16(kreg[s].x, kreg[s].y, hi, lo);
                const int w = kq + 4 * s;
                const int idx = kbase + (kr << 5) + (w ^ ((kr & 7) << 2));
                smw[idx]        = hi;
                smw[idx + 1024] = lo;
            }
            const int vbase = 8192 + cur * 2048;
            #pragma unroll
            for (int i = 0; i < 8; i++) {
                uint32_t hi, lo;
                split_bf16(va[i], vb[i], hi, lo);
                const int n = vn + 8 * i;
                const int idx = vbase + (n << 4) + (vkp ^ (((n >> 1) & 3) << 2));
                smw[idx]        = hi;
                smw[idx + 1024] = lo;
            }
        }
        __syncthreads();

        // ---- prefetch + rope tile kt+1 into regs (overlaps all compute below) ----
        if (kt + 1 < ntiles) {
            const int key1 = (kt + 1) * 32;
            const int krow = key1 + kr;
            const int p = tpos[krow];
            const float* Kr = g_Kraw + (long)(b * SS + krow) * DD + hoff;
            const float* ct = cosT + p * 32;
            const float* st = sinT + p * 32;
            #pragma unroll
            for (int s = 0; s < 8; s++) {
                const int pi = kq + 4 * s;
                float2 v = *(const float2*)(Kr + 2 * pi);
                const float c  = ct[pi];
                const float sn = st[pi];
                kreg[s] = make_float2(c * v.x - sn * v.y, sn * v.x + c * v.y);
            }
            const float* Vr0 = g_Vraw + (long)(b * SS + key1 + 2 * vkp)     * DD + hoff;
            const float* Vr1 = g_Vraw + (long)(b * SS + key1 + 2 * vkp + 1) * DD + hoff;
            #pragma unroll
            for (int i = 0; i < 8; i++) {
                va[i] = Vr0[vn + 8 * i];
                vb[i] = Vr1[vn + 8 * i];
            }
        }

        // ---- S = (Q/8) K^T  (3xBF16, k16; two accumulator chains for ILP) ----
        float S[4][4], S2[4][4];
        #pragma unroll
        for (int fn = 0; fn < 4; fn++)
            #pragma unroll
            for (int r = 0; r < 4; r++) {
                S[fn][r] = 0.0f;
                S2[fn][r] = 0.0f;
            }

        const int kbase = 4096 + cur * 2048;
        #pragma unroll
        for (int kc = 0; kc < 4; kc++) {
            float (*acc)[4] = (kc & 1) ? S2 : S;
            const int w0 = kc * 8 + t;
            const int i00 = (pr0 << 5) + (w0 ^ qsw);
            const int i01 = ((pr0 + 8) << 5) + (w0 ^ qsw);
            const int i10 = (pr0 << 5) + ((w0 + 4) ^ qsw);
            const int i11 = ((pr0 + 8) << 5) + ((w0 + 4) ^ qsw);
            const uint32_t ah0 = smw[i00], ah1 = smw[i01], ah2 = smw[i10], ah3 = smw[i11];
            const uint32_t al0 = smw[2048 + i00], al1 = smw[2048 + i01];
            const uint32_t al2 = smw[2048 + i10], al3 = smw[2048 + i11];

            #pragma unroll
            for (int fn = 0; fn < 4; fn++) {
                const int n = fn * 8 + g;
                const int j0 = kbase + (n << 5) + (w0 ^ qsw);        // (n&7)==g
                const int j1 = kbase + (n << 5) + ((w0 + 4) ^ qsw);
                const uint32_t bh0 = smw[j0], bh1 = smw[j1];
                const uint32_t bl0 = smw[j0 + 1024], bl1 = smw[j1 + 1024];
                mma_bf16(acc[fn], ah0, ah1, ah2, ah3, bh0, bh1);
                mma_bf16(acc[fn], ah0, ah1, ah2, ah3, bl0, bl1);
                mma_bf16(acc[fn], al0, al1, al2, al3, bh0, bh1);
            }
        }
        #pragma unroll
        for (int fn = 0; fn < 4; fn++)
            #pragma unroll
            for (int r = 0; r < 4; r++)
                S[fn][r] += S2[fn][r];

        // ---- causal mask ----
        const int key0 = kt * 32;
        if (kt >= 2 * bx) {
            #pragma unroll
            for (int fn = 0; fn < 4; fn++) {
                const int cg = key0 + fn * 8 + 2 * t;
                if (cg     > r0g) S[fn][0] = -1e30f;
                if (cg + 1 > r0g) S[fn][1] = -1e30f;
                if (cg     > r1g) S[fn][2] = -1e30f;
                if (cg + 1 > r1g) S[fn][3] = -1e30f;
            }
        }

        // ---- online softmax ----
        float mt0 = fmaxf(fmaxf(S[0][0], S[0][1]), fmaxf(S[1][0], S[1][1]));
        mt0 = fmaxf(mt0, fmaxf(fmaxf(S[2][0], S[2][1]), fmaxf(S[3][0], S[3][1])));
        float mt1 = fmaxf(fmaxf(S[0][2], S[0][3]), fmaxf(S[1][2], S[1][3]));
        mt1 = fmaxf(mt1, fmaxf(fmaxf(S[2][2], S[2][3]), fmaxf(S[3][2], S[3][3])));
        mt0 = fmaxf(mt0, __shfl_xor_sync(0xffffffffu, mt0, 1));
        mt0 = fmaxf(mt0, __shfl_xor_sync(0xffffffffu, mt0, 2));
        mt1 = fmaxf(mt1, __shfl_xor_sync(0xffffffffu, mt1, 1));
        mt1 = fmaxf(mt1, __shfl_xor_sync(0xffffffffu, mt1, 2));

        const float m0n = fmaxf(m0, mt0);
        const float m1n = fmaxf(m1, mt1);
        const float a0 = __expf(m0 - m0n);
        const float a1 = __expf(m1 - m1n);

        float P[4][4];
        float ps0 = 0.0f, ps1 = 0.0f;
        #pragma unroll
        for (int fn = 0; fn < 4; fn++) {
            P[fn][0] = __expf(S[fn][0] - m0n);
            P[fn][1] = __expf(S[fn][1] - m0n);
            P[fn][2] = __expf(S[fn][2] - m1n);
            P[fn][3] = __expf(S[fn][3] - m1n);
            ps0 += P[fn][0] + P[fn][1];
            ps1 += P[fn][2] + P[fn][3];
        }
        ps0 += __shfl_xor_sync(0xffffffffu, ps0, 1);
        ps0 += __shfl_xor_sync(0xffffffffu, ps0, 2);
        ps1 += __shfl_xor_sync(0xffffffffu, ps1, 1);
        ps1 += __shfl_xor_sync(0xffffffffu, ps1, 2);

        l0 = l0 * a0 + ps0;
        l1 = l1 * a1 + ps1;
        m0 = m0n;
        m1 = m1n;

        #pragma unroll
        for (int fn = 0; fn < 8; fn++) {
            O[fn][0] *= a0;
            O[fn][1] *= a0;
            O[fn][2] *= a1;
            O[fn][3] *= a1;
        }

        // ---- pack P into PV A-frags directly (C-frag layout == A-frag layout) ----
        uint32_t pah[2][4], pal[2][4];
        #pragma unroll
        for (int kc = 0; kc < 2; kc++) {
            split_bf16(P[2 * kc][0],     P[2 * kc][1],     pah[kc][0], pal[kc][0]);
            split_bf16(P[2 * kc][2],     P[2 * kc][3],     pah[kc][1], pal[kc][1]);
            split_bf16(P[2 * kc + 1][0], P[2 * kc + 1][1], pah[kc][2], pal[kc][2]);
            split_bf16(P[2 * kc + 1][2], P[2 * kc + 1][3], pah[kc][3], pal[kc][3]);
        }

        // ---- O += P V  (3xBF16, k16, V pre-transposed, P from regs) ----
        const int vbase = 8192 + cur * 2048;
        #pragma unroll
        for (int kc = 0; kc < 2; kc++) {
            const int w0 = kc * 8 + t;
            #pragma unroll
            for (int fn = 0; fn < 8; fn++) {
                const int n = fn * 8 + g;
                const int j0 = vbase + (n << 4) + (w0 ^ vsw);
                const int j1 = vbase + (n << 4) + ((w0 + 4) ^ vsw);
                const uint32_t bh0 = smw[j0], bh1 = smw[j1];
                const uint32_t bl0 = smw[j0 + 1024], bl1 = smw[j1 + 1024];
                mma_bf16(O[fn], pah[kc][0], pah[kc][1], pah[kc][2], pah[kc][3], bh0, bh1);
                mma_bf16(O[fn], pah[kc][0], pah[kc][1], pah[kc][2], pah[kc][3], bl0, bl1);
                mma_bf16(O[fn], pal[kc][0], pal[kc][1], pal[kc][2], pal[kc][3], bh0, bh1);
            }
        }
    }

    // ---- epilogue: normalize + write [B,S,H*DK] ----
    const float il0 = 1.0f / l0;
    const float il1 = 1.0f / l1;
    const long o0 = ((long)(b * SS + r0g)) * DD + hoff;
    const long o1 = ((long)(b * SS + r1g)) * DD + hoff;
    #pragma unroll
    for (int fn = 0; fn < 8; fn++) {
        const int col = fn * 8 + 2 * t;
        *(float2*)(g_attn + o0 + col) = make_float2(O[fn][0] * il0, O[fn][1] * il0);
        *(float2*)(g_attn + o1 + col) = make_float2(O[fn][2] * il1, O[fn][3] * il1);
    }
}

// ---------------- launch ----------------
extern "C" void kernel_launch(void* const* d_in, const int* in_sizes, int n_in,
                              void* d_out, int out_size)
{
    (void)in_sizes; (void)n_in; (void)out_size;
    const float* x    = (const float*)d_in[0];
    const int*   tpos = (const int*)  d_in[1];
    const float* W_Q  = (const float*)d_in[2];
    const float* W_K  = (const float*)d_in[3];
    const float* W_V  = (const float*)d_in[4];
    const float* W_O  = (const float*)d_in[5];
    const float* cosT = (const float*)d_in[6];
    const float* sinT = (const float*)d_in[7];
    float* out = (float*)d_out;

    void *pQraw, *pKraw, *pVraw, *pAttn;
    cudaGetSymbolAddress(&pQraw, g_Qraw);
    cudaGetSymbolAddress(&pKraw, g_Kraw);
    cudaGetSymbolAddress(&pVraw, g_Vraw);
    cudaGetSymbolAddress(&pAttn, g_attn);

    static int attn_smem_set = 0;
    if (!attn_smem_set) {
        cudaFuncSetAttribute(flash_attn_kernel,
                             cudaFuncAttributeMaxDynamicSharedMemorySize,
                             ATT_SMEM_WORDS * sizeof(uint32_t));
        attn_smem_set = 1;
    }

    dim3 gblk(256);
    dim3 ggrid(1024 / 128, MM / 128);   // (8, 32)

    gemm_tf32_kernel<<<ggrid, gblk>>>(x, W_Q, (float*)pQraw);
    gemm_tf32_kernel<<<ggrid, gblk>>>(x, W_K, (float*)pKraw);
    gemm_tf32_kernel<<<ggrid, gblk>>>(x, W_V, (float*)pVraw);

    dim3 agrid(SS / 64, BB * HH);        // (32, 32) — launch #4: profiled slot
    flash_attn_kernel<<<agrid, 128, ATT_SMEM_WORDS * sizeof(uint32_t)>>>(tpos, cosT, sinT);

    gemm_tf32_kernel<<<ggrid, gblk>>>((const float*)pAttn, W_O, out);
}

// round 8
// speedup vs baseline: 1.1271x; 1.1271x over previous
#include <cuda_runtime.h>
#include <cuda_bf16.h>
#include <math.h>
#include <stdint.h>
#include <string.h>

#define BB 2
#define SS 2048
#define DD 1024
#define HH 16
#define DK 64
#define MM (BB*SS)   // 4096

// ---------------- scratch (static device memory; no allocations) ----------------
__device__ float g_Qh[BB*SS*DD];   // [B,H,S,DK] rope'd
__device__ float g_Kh[BB*SS*DD];   // [B,H,S,DK] rope'd
__device__ float g_Vh[BB*SS*DD];   // [B,H,S,DK]
__device__ float g_attn[BB*SS*DD]; // [B,S,D]

// ---------------- TF32 helpers (GEMMs) ----------------
__device__ __forceinline__ float to_tf32(float x) {
    float y;
    asm("cvt.rna.tf32.f32 %0, %1;" : "=f"(y) : "f"(x));
    return y;
}

__device__ __forceinline__ void mma_tf32(float c[4],
                                         uint32_t a0, uint32_t a1, uint32_t a2, uint32_t a3,
                                         uint32_t b0, uint32_t b1)
{
    asm volatile("mma.sync.aligned.m16n8k8.row.col.f32.tf32.tf32.f32 "
                 "{%0,%1,%2,%3}, {%4,%5,%6,%7}, {%8,%9}, {%0,%1,%2,%3};"
                 : "+f"(c[0]), "+f"(c[1]), "+f"(c[2]), "+f"(c[3])
                 : "r"(a0), "r"(a1), "r"(a2), "r"(a3), "r"(b0), "r"(b1));
}

// ---------------- BF16 helpers (attention) ----------------
__device__ __forceinline__ void mma_bf16(float c[4],
                                         uint32_t a0, uint32_t a1, uint32_t a2, uint32_t a3,
                                         uint32_t b0, uint32_t b1)
{
    asm volatile("mma.sync.aligned.m16n8k16.row.col.f32.bf16.bf16.f32 "
                 "{%0,%1,%2,%3}, {%4,%5,%6,%7}, {%8,%9}, {%0,%1,%2,%3};"
                 : "+f"(c[0]), "+f"(c[1]), "+f"(c[2]), "+f"(c[3])
                 : "r"(a0), "r"(a1), "r"(a2), "r"(a3), "r"(b0), "r"(b1));
}

// hi = bf16x2(x,y), lo = bf16x2(x-hi.x, y-hi.y); packed as uint32 (even in low half)
__device__ __forceinline__ void split_bf16(float x, float y, uint32_t& hi, uint32_t& lo)
{
    __nv_bfloat162 h = __floats2bfloat162_rn(x, y);
    float hx = __bfloat162float(h.x);
    float hy = __bfloat162float(h.y);
    __nv_bfloat162 l = __floats2bfloat162_rn(x - hx, y - hy);
    hi = *reinterpret_cast<uint32_t*>(&h);
    lo = *reinterpret_cast<uint32_t*>(&l);
}

// ---------------- TF32 GEMM: C = A[4096,1024] @ W[1024,1024] ----------------
// mode 0: plain write to C[M,N]
// mode 1: RoPE + transpose write to C as [B,H,S,DK]
// mode 2: transpose write to C as [B,H,S,DK]
#define AS_STRIDE 20
#define BS_STRIDE 136

__global__ void __launch_bounds__(256, 2)
gemm_tf32_kernel(const float* __restrict__ A, const float* __restrict__ W,
                 float* __restrict__ C, int mode,
                 const int* __restrict__ tpos,
                 const float* __restrict__ cosT,
                 const float* __restrict__ sinT)
{
    const int K = 1024, N = 1024;
    __shared__ float As[128 * AS_STRIDE];
    __shared__ float Bs[16 * BS_STRIDE];

    const int tid  = threadIdx.x;
    const int warp = tid >> 5;
    const int lane = tid & 31;
    const int g = lane >> 2;
    const int t = lane & 3;

    const int wm = warp & 1;
    const int wn = warp >> 1;
    const int warp_m = wm * 64;
    const int warp_n = wn * 32;

    const int row0 = blockIdx.y * 128;
    const int col0 = blockIdx.x * 128;

    const int a_row = tid >> 1;
    const int a_cg  = (tid & 1) * 8;
    const int b_row = tid >> 4;
    const int b_col = (tid & 15) * 8;

    float acc[4][4][4];
    #pragma unroll
    for (int i = 0; i < 4; i++)
        #pragma unroll
        for (int j = 0; j < 4; j++)
            #pragma unroll
            for (int r = 0; r < 4; r++)
                acc[i][j][r] = 0.0f;

    for (int k0 = 0; k0 < K; k0 += 16) {
        {
            const float4* src = (const float4*)&A[(long)(row0 + a_row) * K + k0 + a_cg];
            float4 v0 = src[0];
            float4 v1 = src[1];
            float4 w0 = make_float4(to_tf32(v0.x), to_tf32(v0.y), to_tf32(v0.z), to_tf32(v0.w));
            float4 w1 = make_float4(to_tf32(v1.x), to_tf32(v1.y), to_tf32(v1.z), to_tf32(v1.w));
            float4* dst = (float4*)&As[a_row * AS_STRIDE + a_cg];
            dst[0] = w0;
            dst[1] = w1;
        }
        {
            const float4* src = (const float4*)&W[(long)(k0 + b_row) * N + col0 + b_col];
            float4 v0 = src[0];
            float4 v1 = src[1];
            float4 w0 = make_float4(to_tf32(v0.x), to_tf32(v0.y), to_tf32(v0.z), to_tf32(v0.w));
            float4 w1 = make_float4(to_tf32(v1.x), to_tf32(v1.y), to_tf32(v1.z), to_tf32(v1.w));
            float4* dst = (float4*)&Bs[b_row * BS_STRIDE + b_col];
            dst[0] = w0;
            dst[1] = w1;
        }
        __syncthreads();

        #pragma unroll
        for (int chunk = 0; chunk < 2; chunk++) {
            const int kc = chunk * 8;

            uint32_t af[4][4];
            #pragma unroll
            for (int fm = 0; fm < 4; fm++) {
                int mrow = warp_m + fm * 16 + g;
                const float* pa = &As[mrow * AS_STRIDE + kc + t];
                af[fm][0] = __float_as_uint(pa[0]);
                af[fm][1] = __float_as_uint(pa[8 * AS_STRIDE]);
                af[fm][2] = __float_as_uint(pa[4]);
                af[fm][3] = __float_as_uint(pa[8 * AS_STRIDE + 4]);
            }
            uint32_t bf[4][2];
            #pragma unroll
            for (int fn = 0; fn < 4; fn++) {
                const float* pb = &Bs[(kc + t) * BS_STRIDE + warp_n + fn * 8 + g];
                bf[fn][0] = __float_as_uint(pb[0]);
                bf[fn][1] = __float_as_uint(pb[4 * BS_STRIDE]);
            }

            #pragma unroll
            for (int fm = 0; fm < 4; fm++)
                #pragma unroll
                for (int fn = 0; fn < 4; fn++)
                    mma_tf32(acc[fm][fn],
                             af[fm][0], af[fm][1], af[fm][2], af[fm][3],
                             bf[fn][0], bf[fn][1]);
        }
        __syncthreads();
    }

    if (mode == 0) {
        #pragma unroll
        for (int fm = 0; fm < 4; fm++) {
            #pragma unroll
            for (int fn = 0; fn < 4; fn++) {
                int r0 = row0 + warp_m + fm * 16 + g;
                int c0 = col0 + warp_n + fn * 8 + 2 * t;
                *(float2*)&C[(long)r0 * N + c0] =
                    make_float2(acc[fm][fn][0], acc[fm][fn][1]);
                *(float2*)&C[(long)(r0 + 8) * N + c0] =
                    make_float2(acc[fm][fn][2], acc[fm][fn][3]);
            }
        }
    } else {
        #pragma unroll
        for (int fm = 0; fm < 4; fm++) {
            const int m0r = row0 + warp_m + fm * 16 + g;   // token index
            const int bb = m0r >> 11;
            const int s0 = m0r & 2047;
            const int s1 = s0 + 8;
            const int p0 = tpos[s0];
            const int p1 = tpos[s1];
            #pragma unroll
            for (int fn = 0; fn < 4; fn++) {
                const int c0 = col0 + warp_n + fn * 8 + 2 * t;
                const int hh = c0 >> 6;
                const int d  = c0 & 63;
                const int pi = d >> 1;
                float x0 = acc[fm][fn][0], y0 = acc[fm][fn][1];
                float x1 = acc[fm][fn][2], y1 = acc[fm][fn][3];
                if (mode == 1) {
                    float cc = cosT[p0 * 32 + pi], ssn = sinT[p0 * 32 + pi];
                    float xe = cc * x0 - ssn * y0;
                    float xo = ssn * x0 + cc * y0;
                    x0 = xe; y0 = xo;
                    cc = cosT[p1 * 32 + pi]; ssn = sinT[p1 * 32 + pi];
                    xe = cc * x1 - ssn * y1;
                    xo = ssn * x1 + cc * y1;
                    x1 = xe; y1 = xo;
                }
                const long rbase = (long)(bb * HH + hh) * SS;
                *(float2*)&C[(rbase + s0) * DK + d] = make_float2(x0, y0);
                *(float2*)&C[(rbase + s1) * DK + d] = make_float2(x1, y1);
            }
        }
    }
}

// ---------------- flash attention (3xBF16 mma m16n8k16, causal) ----------------
// Br=64 (4 warps x 16 rows), Bc=32, single-buffered, 32 KB static smem,
// target 5 blocks/SM (20 warps). Q/K/V pre-split into packed bf16x2 hi/lo
// planes; P stays in registers (S C-frags map directly onto PV A-frags).
//
// smem word map (uint32):
//  sQ : [pl][64 r][32 w]   idx =        pl*2048 + (r<<5) + (w ^ ((r&7)<<2))
//  sK : [pl][32 r][32 w]   idx = 4096 + pl*1024 + (r<<5) + (w ^ ((r&7)<<2))
//  sVT: [pl][64 n][16 kp]  idx = 6144 + pl*1024 + (n<<4) + (kp ^ (((n>>1)&3)<<2))
__global__ void __launch_bounds__(128, 5)
flash_attn_kernel()
{
    __shared__ uint32_t smw[8192];   // 32 KB

    const int tid  = threadIdx.x;
    const int warp = tid >> 5;
    const int lane = tid & 31;
    const int g = lane >> 2;
    const int t = lane & 3;

    const int bx = gridDim.x - 1 - blockIdx.x;   // heavy tiles first
    const int bh = blockIdx.y;
    const int b = bh >> 4, h = bh & 15;
    const long hb = (long)bh * SS * DK;
    const int q0 = bx * 64;

    // ---- stage Q once (scale 1/8, bf16 hi/lo planes) ----
    {
        const float* Qg = g_Qh + hb + (long)q0 * DK;
        const int row = tid >> 1;
        #pragma unroll
        for (int s = 0; s < 16; s++) {
            const int w = (tid & 1) + 2 * s;
            float2 v = *(const float2*)(Qg + row * DK + 2 * w);
            uint32_t hi, lo;
            split_bf16(v.x * 0.125f, v.y * 0.125f, hi, lo);
            const int idx = (row << 5) + (w ^ ((row & 7) << 2));
            smw[idx]        = hi;
            smw[idx + 2048] = lo;
        }
    }

    const int kr  = tid >> 2;        // K staging row 0..31
    const int kq  = tid & 3;         // K word phase
    const int vkp = tid >> 3;        // V key-pair 0..15
    const int vn  = tid & 7;         // V dim phase

    float m0 = -1e30f, m1 = -1e30f, l0 = 0.0f, l1 = 0.0f;
    float O[8][4];
    #pragma unroll
    for (int fn = 0; fn < 8; fn++)
        #pragma unroll
        for (int r = 0; r < 4; r++)
            O[fn][r] = 0.0f;

    const int pr0 = warp * 16 + g;
    const int r0g = q0 + pr0;
    const int r1g = r0g + 8;
    const int ntiles = 2 * bx + 2;

    const int qsw = g << 2;
    const int vsw = ((g >> 1) & 3) << 2;

    for (int kt = 0; kt < ntiles; kt++) {
        __syncthreads();   // previous tile fully consumed (covers Q staging at kt=0)

        // ---- stage K tile (rope'd, contiguous rows) ----
        {
            const float* Kr = g_Kh + hb + (long)(kt * 32 + kr) * DK;
            #pragma unroll
            for (int s = 0; s < 8; s++) {
                float2 v = *(const float2*)(Kr + 2 * (kq + 4 * s));
                uint32_t hi, lo;
                split_bf16(v.x, v.y, hi, lo);
                const int w = kq + 4 * s;
                const int idx = 4096 + (kr << 5) + (w ^ ((kr & 7) << 2));
                smw[idx]        = hi;
                smw[idx + 1024] = lo;
            }
            const float* Vr = g_Vh + hb + (long)(kt * 32 + 2 * vkp) * DK;
            #pragma unroll
            for (int i = 0; i < 8; i++) {
                uint32_t hi, lo;
                split_bf16(Vr[vn + 8 * i], Vr[DK + vn + 8 * i], hi, lo);
                const int n = vn + 8 * i;
                const int idx = 6144 + (n << 4) + (vkp ^ (((n >> 1) & 3) << 2));
                smw[idx]        = hi;
                smw[idx + 1024] = lo;
            }
        }
        __syncthreads();

        // ---- S = (Q/8) K^T  (3xBF16, k16) ----
        float S[4][4];
        #pragma unroll
        for (int fn = 0; fn < 4; fn++)
            #pragma unroll
            for (int r = 0; r < 4; r++)
                S[fn][r] = 0.0f;

        #pragma unroll
        for (int kc = 0; kc < 4; kc++) {
            const int w0 = kc * 8 + t;
            const int i00 = (pr0 << 5) + (w0 ^ qsw);
            const int i01 = ((pr0 + 8) << 5) + (w0 ^ qsw);
            const int i10 = (pr0 << 5) + ((w0 + 4) ^ qsw);
            const int i11 = ((pr0 + 8) << 5) + ((w0 + 4) ^ qsw);
            const uint32_t ah0 = smw[i00], ah1 = smw[i01], ah2 = smw[i10], ah3 = smw[i11];
            const uint32_t al0 = smw[2048 + i00], al1 = smw[2048 + i01];
            const uint32_t al2 = smw[2048 + i10], al3 = smw[2048 + i11];

            #pragma unroll
            for (int fn = 0; fn < 4; fn++) {
                const int n = fn * 8 + g;
                const int j0 = 4096 + (n << 5) + (w0 ^ qsw);        // (n&7)==g
                const int j1 = 4096 + (n << 5) + ((w0 + 4) ^ qsw);
                const uint32_t bh0 = smw[j0], bh1 = smw[j1];
                const uint32_t bl0 = smw[j0 + 1024], bl1 = smw[j1 + 1024];
                mma_bf16(S[fn], ah0, ah1, ah2, ah3, bh0, bh1);
                mma_bf16(S[fn], ah0, ah1, ah2, ah3, bl0, bl1);
                mma_bf16(S[fn], al0, al1, al2, al3, bh0, bh1);
            }
        }

        // ---- causal mask ----
        const int key0 = kt * 32;
        if (kt >= 2 * bx) {
            #pragma unroll
            for (int fn = 0; fn < 4; fn++) {
                const int cg = key0 + fn * 8 + 2 * t;
                if (cg     > r0g) S[fn][0] = -1e30f;
                if (cg + 1 > r0g) S[fn][1] = -1e30f;
                if (cg     > r1g) S[fn][2] = -1e30f;
                if (cg + 1 > r1g) S[fn][3] = -1e30f;
            }
        }

        // ---- online softmax (P computed in place into S) ----
        float mt0 = fmaxf(fmaxf(S[0][0], S[0][1]), fmaxf(S[1][0], S[1][1]));
        mt0 = fmaxf(mt0, fmaxf(fmaxf(S[2][0], S[2][1]), fmaxf(S[3][0], S[3][1])));
        float mt1 = fmaxf(fmaxf(S[0][2], S[0][3]), fmaxf(S[1][2], S[1][3]));
        mt1 = fmaxf(mt1, fmaxf(fmaxf(S[2][2], S[2][3]), fmaxf(S[3][2], S[3][3])));
        mt0 = fmaxf(mt0, __shfl_xor_sync(0xffffffffu, mt0, 1));
        mt0 = fmaxf(mt0, __shfl_xor_sync(0xffffffffu, mt0, 2));
        mt1 = fmaxf(mt1, __shfl_xor_sync(0xffffffffu, mt1, 1));
        mt1 = fmaxf(mt1, __shfl_xor_sync(0xffffffffu, mt1, 2));

        const float m0n = fmaxf(m0, mt0);
        const float m1n = fmaxf(m1, mt1);
        const float a0 = __expf(m0 - m0n);
        const float a1 = __expf(m1 - m1n);

        float ps0 = 0.0f, ps1 = 0.0f;
        #pragma unroll
        for (int fn = 0; fn < 4; fn++) {
            S[fn][0] = __expf(S[fn][0] - m0n);
            S[fn][1] = __expf(S[fn][1] - m0n);
            S[fn][2] = __expf(S[fn][2] - m1n);
            S[fn][3] = __expf(S[fn][3] - m1n);
            ps0 += S[fn][0] + S[fn][1];
            ps1 += S[fn][2] + S[fn][3];
        }
        ps0 += __shfl_xor_sync(0xffffffffu, ps0, 1);
        ps0 += __shfl_xor_sync(0xffffffffu, ps0, 2);
        ps1 += __shfl_xor_sync(0xffffffffu, ps1, 1);
        ps1 += __shfl_xor_sync(0xffffffffu, ps1, 2);

        l0 = l0 * a0 + ps0;
        l1 = l1 * a1 + ps1;
        m0 = m0n;
        m1 = m1n;

        #pragma unroll
        for (int fn = 0; fn < 8; fn++) {
            O[fn][0] *= a0;
            O[fn][1] *= a0;
            O[fn][2] *= a1;
            O[fn][3] *= a1;
        }

        // ---- pack P into PV A-frags directly (C-frag layout == A-frag layout) ----
        uint32_t pah[2][4], pal[2][4];
        #pragma unroll
        for (int kc = 0; kc < 2; kc++) {
            split_bf16(S[2 * kc][0],     S[2 * kc][1],     pah[kc][0], pal[kc][0]);
            split_bf16(S[2 * kc][2],     S[2 * kc][3],     pah[kc][1], pal[kc][1]);
            split_bf16(S[2 * kc + 1][0], S[2 * kc + 1][1], pah[kc][2], pal[kc][2]);
            split_bf16(S[2 * kc + 1][2], S[2 * kc + 1][3], pah[kc][3], pal[kc][3]);
        }

        // ---- O += P V  (3xBF16, k16, V pre-transposed, P from regs) ----
        #pragma unroll
        for (int kc = 0; kc < 2; kc++) {
            const int w0 = kc * 8 + t;
            #pragma unroll
            for (int fn = 0; fn < 8; fn++) {
                const int n = fn * 8 + g;
                const int j0 = 6144 + (n << 4) + (w0 ^ vsw);
                const int j1 = 6144 + (n << 4) + ((w0 + 4) ^ vsw);
                const uint32_t bh0 = smw[j0], bh1 = smw[j1];
                const uint32_t bl0 = smw[j0 + 1024], bl1 = smw[j1 + 1024];
                mma_bf16(O[fn], pah[kc][0], pah[kc][1], pah[kc][2], pah[kc][3], bh0, bh1);
                mma_bf16(O[fn], pah[kc][0], pah[kc][1], pah[kc][2], pah[kc][3], bl0, bl1);
                mma_bf16(O[fn], pal[kc][0], pal[kc][1], pal[kc][2], pal[kc][3], bh0, bh1);
            }
        }
    }

    // ---- epilogue: normalize + write [B,S,H*DK] ----
    const float il0 = 1.0f / l0;
    const float il1 = 1.0f / l1;
    const long o0 = ((long)(b * SS + r0g)) * DD + (long)h * DK;
    const long o1 = ((long)(b * SS + r1g)) * DD + (long)h * DK;
    #pragma unroll
    for (int fn = 0; fn < 8; fn++) {
        const int col = fn * 8 + 2 * t;
        *(float2*)(g_attn + o0 + col) = make_float2(O[fn][0] * il0, O[fn][1] * il0);
        *(float2*)(g_attn + o1 + col) = make_float2(O[fn][2] * il1, O[fn][3] * il1);
    }
}

// ---------------- launch ----------------
extern "C" void kernel_launch(void* const* d_in, const int* in_sizes, int n_in,
                              void* d_out, int out_size)
{
    (void)in_sizes; (void)n_in; (void)out_size;
    const float* x    = (const float*)d_in[0];
    const int*   tpos = (const int*)  d_in[1];
    const float* W_Q  = (const float*)d_in[2];
    const float* W_K  = (const float*)d_in[3];
    const float* W_V  = (const float*)d_in[4];
    const float* W_O  = (const float*)d_in[5];
    const float* cosT = (const float*)d_in[6];
    const float* sinT = (const float*)d_in[7];
    float* out = (float*)d_out;

    void *pQh, *pKh, *pVh, *pAttn;
    cudaGetSymbolAddress(&pQh, g_Qh);
    cudaGetSymbolAddress(&pKh, g_Kh);
    cudaGetSymbolAddress(&pVh, g_Vh);
    cudaGetSymbolAddress(&pAttn, g_attn);

    dim3 gblk(256);
    dim3 ggrid(1024 / 128, MM / 128);   // (8, 32)

    gemm_tf32_kernel<<<ggrid, gblk>>>(x, W_Q, (float*)pQh, 1, tpos, cosT, sinT);
    gemm_tf32_kernel<<<ggrid, gblk>>>(x, W_K, (float*)pKh, 1, tpos, cosT, sinT);
    gemm_tf32_kernel<<<ggrid, gblk>>>(x, W_V, (float*)pVh, 2, tpos, cosT, sinT);

    dim3 agrid(SS / 64, BB * HH);        // (32, 32) — launch #4: profiled slot
    flash_attn_kernel<<<agrid, 128>>>();

    gemm_tf32_kernel<<<ggrid, gblk>>>((const float*)pAttn, W_O, out, 0, tpos, cosT, sinT);
}